// round 13
// baseline (speedup 1.0000x reference)
#include <cuda_runtime.h>

// WarpDTI fused, z-pair thread coarsening: one thread handles voxels (2l, 2l+1),
// a warp covers a full 64-z row. All DDF traffic is float2 (LDG.64) shared by
// the pair; z-gradient comes from the pair partner + 1 shuffle per channel with
// branch-free one-sided boundaries; outputs are STG.64. Gather stays scalar
// planar (coalescing-optimal, proven R9/R10). Polar: 2 scaled + 4 plain Newton.

constexpr int HWD = 64 * 64 * 64;   // 262144 = 2^18

__device__ __forceinline__ void polar_reorient(
    float J00, float J01, float J02,
    float J10, float J11, float J12,
    float J20, float J21, float J22,
    const float m[6], float S[6])
{
    float X00 = J00, X01 = J01, X02 = J02;
    float X10 = J10, X11 = J11, X12 = J12;
    float X20 = J20, X21 = J21, X22 = J22;

    // 2 scaled Newton iterations (Frobenius mu, fast-math — self-correcting)
    #pragma unroll
    for (int it = 0; it < 2; ++it) {
        float C00 = X11 * X22 - X12 * X21;
        float C01 = X12 * X20 - X10 * X22;
        float C02 = X10 * X21 - X11 * X20;
        float C10 = X21 * X02 - X22 * X01;
        float C11 = X22 * X00 - X20 * X02;
        float C12 = X20 * X01 - X21 * X00;
        float C20 = X01 * X12 - X02 * X11;
        float C21 = X02 * X10 - X00 * X12;
        float C22 = X00 * X11 - X01 * X10;
        float det = X00 * C00 + X01 * C01 + X02 * C02;
        float adet = fmaxf(fabsf(det), 1e-12f);
        float sdet = (det < 0.0f) ? -adet : adet;
        float nX = X00*X00 + X01*X01 + X02*X02 + X10*X10 + X11*X11 + X12*X12
                 + X20*X20 + X21*X21 + X22*X22;
        float nC = C00*C00 + C01*C01 + C02*C02 + C10*C10 + C11*C11 + C12*C12
                 + C20*C20 + C21*C21 + C22*C22;
        float mu = exp2f(0.25f * __log2f(nC / nX)) * rsqrtf(adet);
        mu = fminf(fmaxf(mu, 1e-4f), 1e4f);
        float a = 0.5f * mu;
        float c = __fdividef(0.5f, mu * sdet);
        X00 = a * X00 + c * C00; X01 = a * X01 + c * C01; X02 = a * X02 + c * C02;
        X10 = a * X10 + c * C10; X11 = a * X11 + c * C11; X12 = a * X12 + c * C12;
        X20 = a * X20 + c * C20; X21 = a * X21 + c * C21; X22 = a * X22 + c * C22;
    }
    // 4 plain Newton iterations: X <- 0.5*(X + cof(X)/det)
    #pragma unroll
    for (int it = 0; it < 4; ++it) {
        float C00 = X11 * X22 - X12 * X21;
        float C01 = X12 * X20 - X10 * X22;
        float C02 = X10 * X21 - X11 * X20;
        float C10 = X21 * X02 - X22 * X01;
        float C11 = X22 * X00 - X20 * X02;
        float C12 = X20 * X01 - X21 * X00;
        float C20 = X01 * X12 - X02 * X11;
        float C21 = X02 * X10 - X00 * X12;
        float C22 = X00 * X11 - X01 * X10;
        float det = X00 * C00 + X01 * C01 + X02 * C02;
        float adet = fmaxf(fabsf(det), 1e-12f);
        float sdet = (det < 0.0f) ? -adet : adet;
        float c = __fdividef(0.5f, sdet);
        X00 = 0.5f * X00 + c * C00; X01 = 0.5f * X01 + c * C01; X02 = 0.5f * X02 + c * C02;
        X10 = 0.5f * X10 + c * C10; X11 = 0.5f * X11 + c * C11; X12 = 0.5f * X12 + c * C12;
        X20 = 0.5f * X20 + c * C20; X21 = 0.5f * X21 + c * C21; X22 = 0.5f * X22 + c * C22;
    }

    float w0x = m[0]*X00 + m[1]*X10 + m[3]*X20;
    float w0y = m[1]*X00 + m[2]*X10 + m[4]*X20;
    float w0z = m[3]*X00 + m[4]*X10 + m[5]*X20;
    float w1x = m[0]*X01 + m[1]*X11 + m[3]*X21;
    float w1y = m[1]*X01 + m[2]*X11 + m[4]*X21;
    float w1z = m[3]*X01 + m[4]*X11 + m[5]*X21;
    float w2x = m[0]*X02 + m[1]*X12 + m[3]*X22;
    float w2y = m[1]*X02 + m[2]*X12 + m[4]*X22;
    float w2z = m[3]*X02 + m[4]*X12 + m[5]*X22;

    S[0] = X00*w0x + X10*w0y + X20*w0z;   // (0,0)
    S[1] = X01*w0x + X11*w0y + X21*w0z;   // (1,0)
    S[2] = X01*w1x + X11*w1y + X21*w1z;   // (1,1)
    S[3] = X02*w0x + X12*w0y + X22*w0z;   // (2,0)
    S[4] = X02*w1x + X12*w1y + X22*w1z;   // (2,1)
    S[5] = X02*w2x + X12*w2y + X22*w2z;   // (2,2)
}

__device__ __forceinline__ void gather_m(
    const float* __restrict__ img,   // dti + b*6*HWD
    int x, int y, int z,
    float u0, float u1, float u2,
    float m[6])
{
    float cx = fminf(fmaxf(u0 + (float)x, 0.0f), 63.0f);
    float cy = fminf(fmaxf(u1 + (float)y, 0.0f), 63.0f);
    float cz = fminf(fmaxf(u2 + (float)z, 0.0f), 63.0f);
    float xf = floorf(cx), yf = floorf(cy), zf = floorf(cz);
    float fx = cx - xf,   fy = cy - yf,   fz = cz - zf;
    int x0 = (int)xf, y0 = (int)yf, z0 = (int)zf;
    int x1 = min(x0 + 1, 63), y1 = min(y0 + 1, 63), z1 = min(z0 + 1, 63);

    int b00 = ((x0 << 6) + y0) << 6;
    int b01 = ((x0 << 6) + y1) << 6;
    int b10 = ((x1 << 6) + y0) << 6;
    int b11 = ((x1 << 6) + y1) << 6;

    float wx0 = 1.0f - fx, wy0 = 1.0f - fy, wz0 = 1.0f - fz;
    float w000 = wx0 * wy0 * wz0, w001 = wx0 * wy0 * fz;
    float w010 = wx0 * fy  * wz0, w011 = wx0 * fy  * fz;
    float w100 = fx  * wy0 * wz0, w101 = fx  * wy0 * fz;
    float w110 = fx  * fy  * wz0, w111 = fx  * fy  * fz;

    #pragma unroll
    for (int c = 0; c < 6; c++) {
        const float* p = img + c * HWD;
        m[c] = w000 * __ldg(p + b00 + z0) + w001 * __ldg(p + b00 + z1)
             + w010 * __ldg(p + b01 + z0) + w011 * __ldg(p + b01 + z1)
             + w100 * __ldg(p + b10 + z0) + w101 * __ldg(p + b10 + z1)
             + w110 * __ldg(p + b11 + z0) + w111 * __ldg(p + b11 + z1);
    }
}

__global__ __launch_bounds__(256)
void warp_dti_kernel(const float* __restrict__ dti,
                     const float* __restrict__ ddf,
                     float* __restrict__ out,
                     int total_pairs)
{
    int pid = blockIdx.x * blockDim.x + threadIdx.x;
    if (pid >= total_pairs) return;

    int vox = (pid << 1) & (HWD - 1);     // even
    int b   = pid >> 17;                  // (pid*2) >> 18
    int zlo =  vox        & 63;           // even; zhi = zlo + 1
    int y   = (vox >> 6)  & 63;
    int x   =  vox >> 12;
    unsigned lane = threadIdx.x & 31;

    const float2* u2p = (const float2*)(ddf + (size_t)b * 3 * HWD);
    int h = vox >> 1;                     // float2 index of this pair
    constexpr int H2 = HWD / 2;

    // center displacements: .x = lo voxel, .y = hi voxel
    float2 c0 = __ldg(u2p +          h);
    float2 c1 = __ldg(u2p +     H2 + h);
    float2 c2 = __ldg(u2p + 2 * H2 + h);

    // ---------- Jacobian (jnp.gradient: central interior, one-sided edges) ----
    float J00l, J01l, J02l, J10l, J11l, J12l, J20l, J21l, J22l;
    float J00h, J01h, J02h, J10h, J11h, J12h, J20h, J21h, J22h;
    {   // axis 0 (x): float2 stride 2048
        int ip = (x < 63) ? x + 1 : 63;
        int im = (x > 0 ) ? x - 1 : 0;
        float s = (ip - im == 2) ? 0.5f : 1.0f;
        int op = (ip - x) << 11, om = (im - x) << 11;
        float2 p0 = __ldg(u2p +          h + op), q0 = __ldg(u2p +          h + om);
        float2 p1 = __ldg(u2p +     H2 + h + op), q1 = __ldg(u2p +     H2 + h + om);
        float2 p2 = __ldg(u2p + 2 * H2 + h + op), q2 = __ldg(u2p + 2 * H2 + h + om);
        J00l = (p0.x - q0.x) * s;  J00h = (p0.y - q0.y) * s;
        J10l = (p1.x - q1.x) * s;  J10h = (p1.y - q1.y) * s;
        J20l = (p2.x - q2.x) * s;  J20h = (p2.y - q2.y) * s;
    }
    {   // axis 1 (y): float2 stride 32
        int ip = (y < 63) ? y + 1 : 63;
        int im = (y > 0 ) ? y - 1 : 0;
        float s = (ip - im == 2) ? 0.5f : 1.0f;
        int op = (ip - y) << 5, om = (im - y) << 5;
        float2 p0 = __ldg(u2p +          h + op), q0 = __ldg(u2p +          h + om);
        float2 p1 = __ldg(u2p +     H2 + h + op), q1 = __ldg(u2p +     H2 + h + om);
        float2 p2 = __ldg(u2p + 2 * H2 + h + op), q2 = __ldg(u2p + 2 * H2 + h + om);
        J01l = (p0.x - q0.x) * s;  J01h = (p0.y - q0.y) * s;
        J11l = (p1.x - q1.x) * s;  J11h = (p1.y - q1.y) * s;
        J21l = (p2.x - q2.x) * s;  J21h = (p2.y - q2.y) * s;
    }
    {   // axis 2 (z): pair partner + one shuffle per direction; boundaries
        // (z=0 at lane0.lo, z=63 at lane31.hi) are one-sided using ONLY the
        // thread's own pair: u(1)-u(0) = hi-lo, u(63)-u(62) = hi-lo.
        float pu0 = __shfl_up_sync(0xFFFFFFFFu, c0.y, 1);
        float pu1 = __shfl_up_sync(0xFFFFFFFFu, c1.y, 1);
        float pu2 = __shfl_up_sync(0xFFFFFFFFu, c2.y, 1);
        float dn0 = __shfl_down_sync(0xFFFFFFFFu, c0.x, 1);
        float dn1 = __shfl_down_sync(0xFFFFFFFFu, c1.x, 1);
        float dn2 = __shfl_down_sync(0xFFFFFFFFu, c2.x, 1);
        bool e0 = (lane == 0), e31 = (lane == 31);
        J02l = e0  ? (c0.y - c0.x) : 0.5f * (c0.y - pu0);
        J12l = e0  ? (c1.y - c1.x) : 0.5f * (c1.y - pu1);
        J22l = e0  ? (c2.y - c2.x) : 0.5f * (c2.y - pu2);
        J02h = e31 ? (c0.y - c0.x) : 0.5f * (dn0 - c0.x);
        J12h = e31 ? (c1.y - c1.x) : 0.5f * (dn1 - c1.x);
        J22h = e31 ? (c2.y - c2.x) : 0.5f * (dn2 - c2.x);
    }
    J00l += 1.0f; J11l += 1.0f; J22l += 1.0f;
    J00h += 1.0f; J11h += 1.0f; J22h += 1.0f;

    const float* img = dti + (size_t)b * 6 * HWD;

    // ---------- voxel lo ----------
    float mlo[6], Slo[6];
    gather_m(img, x, y, zlo, c0.x, c1.x, c2.x, mlo);
    polar_reorient(J00l, J01l, J02l, J10l, J11l, J12l, J20l, J21l, J22l, mlo, Slo);

    // ---------- voxel hi ----------
    float mhi[6], Shi[6];
    gather_m(img, x, y, zlo + 1, c0.y, c1.y, c2.y, mhi);
    polar_reorient(J00h, J01h, J02h, J10h, J11h, J12h, J20h, J21h, J22h, mhi, Shi);

    // ---------- paired stores (STG.64, planar channels) ----------
    float2* o = (float2*)(out + (size_t)b * 6 * HWD);
    #pragma unroll
    for (int c = 0; c < 6; c++)
        o[c * H2 + h] = make_float2(Slo[c], Shi[c]);
}

extern "C" void kernel_launch(void* const* d_in, const int* in_sizes, int n_in,
                              void* d_out, int out_size)
{
    const float* dti = (const float*)d_in[0];
    const float* ddf = (const float*)d_in[1];
    int s0 = in_sizes[0], s1 = in_sizes[1];
    if (s0 < s1) { const float* t = dti; dti = ddf; ddf = t; int ts = s0; s0 = s1; s1 = ts; }
    int B = s1 / (3 * HWD);
    int total_pairs = B * (HWD / 2);
    int threads = 256;
    int blocks = (total_pairs + threads - 1) / threads;
    warp_dti_kernel<<<blocks, threads>>>(dti, ddf, (float*)d_out, total_pairs);
}